// round 15
// baseline (speedup 1.0000x reference)
#include <cuda_runtime.h>
#include <cuda_bf16.h>
#include <cuda_fp16.h>
#include <math.h>
#include <cstdint>

// Problem dims
#define LL 512
#define BB 64
#define II 256
#define HH 512
#define G4 2048   // 4*H

// ---------------- scratch (static device globals; no allocation) ----------------
__device__ float g_gates_f[(size_t)LL * BB * G4];     // [t][b][4H]
__device__ float g_gates_r[(size_t)LL * BB * G4];     // [t][b][4H]
__device__ unsigned g_bar8[8 * 32];                   // (dir,bs,phase) barriers, 128B apart

// h state as SINGLE fp16: [dir][parity][b][u]
__device__ __align__(16) __half g_sh16[2 * 2 * BB * HH];

// fp16 GEMM operands: A single (layer0: xT fp16; layer1: hcat fp16), W single per dir
__device__ __align__(16) __half g_Af16[(size_t)LL * BB * 2 * HH];
__device__ __align__(16) __half g_Wf16f[(size_t)G4 * 2 * HH];
__device__ __align__(16) __half g_Wf16r[(size_t)G4 * 2 * HH];
// Whh fp16 (single) for the recurrence ([2048][512] each)
__device__ __align__(16) __half g_Whf16f[(size_t)G4 * HH];
__device__ __align__(16) __half g_Whf16r[(size_t)G4 * HH];

__device__ __forceinline__ uint32_t smem_u32(const void* p) {
    uint32_t a;
    asm("{ .reg .u64 t; cvta.to.shared.u64 t, %1; cvt.u32.u64 %0, t; }" : "=r"(a) : "l"(p));
    return a;
}

__device__ __forceinline__ float fsig(float x) {
    return 1.0f / (1.0f + __expf(-x));
}
__device__ __forceinline__ float ftanh(float x) {
    return fmaf(2.0f, fsig(2.0f * x), -1.0f);
}

// ---------------- transpose + convert: x[b][l][i] fp32 -> Af16[l*BB+b][i] fp16 ----------------
__global__ void transpose_cvt_x(const float4* __restrict__ x, __half2* __restrict__ xT) {
    int idx = blockIdx.x * blockDim.x + threadIdx.x;
    int i4 = idx & 63;
    int m  = idx >> 6;
    int t  = m >> 6;
    int b  = m & 63;
    float4 v = x[((size_t)(b * LL + t)) * 64 + i4];
    xT[idx * 2 + 0] = __floats2half2_rn(v.x, v.y);
    xT[idx * 2 + 1] = __floats2half2_rn(v.z, v.w);
}

// ---------------- fp32 -> fp16 convert ----------------
__global__ void cvt_f16(const float4* __restrict__ src, __half2* __restrict__ dst, int n4) {
    int i = blockIdx.x * blockDim.x + threadIdx.x;
    if (i >= n4) return;
    float4 v = src[i];
    dst[i * 2 + 0] = __floats2half2_rn(v.x, v.y);
    dst[i * 2 + 1] = __floats2half2_rn(v.z, v.w);
}

// ---------------- plain fp16 GEMM (unchanged, known-good: 912 TF/s measured) ----------------
#define GBK   32
#define GTILE 10240
#define GSTG  (2 * GTILE)
#define GB_SMEM (2 * GSTG + 512)

__global__ __launch_bounds__(256, 2) void gemm_f16(
    int M, int N, int K,
    const __half* __restrict__ A,
    const __half* __restrict__ B,
    const float* __restrict__ bias1, const float* __restrict__ bias2,
    float* __restrict__ C)
{
    extern __shared__ char sm[];
    uint32_t sb = smem_u32(sm);
    int tid  = threadIdx.x;
    int lane = tid & 31;
    int warp = tid >> 5;
    int gid  = lane >> 2;
    int tg   = lane & 3;
    int wm   = warp >> 2;
    int wn   = warp & 3;
    int n0   = blockIdx.x * 128;
    int m0   = blockIdx.y * 128;

    float* shb = (float*)(sm + 2 * GSTG);
    if (tid < 128) shb[tid] = bias1[n0 + tid] + bias2[n0 + tid];

    const char* srcs[2];
    srcs[0] = (const char*)(A + (size_t)m0 * K);
    srcs[1] = (const char*)(B + (size_t)n0 * K);

#define LOAD_STAGE(kc, bufsel)                                                      \
    {                                                                               \
        _Pragma("unroll")                                                           \
        for (int j = 0; j < 4; j++) {                                               \
            int c    = tid + j * 256;                                               \
            int tile = c >> 9;                                                      \
            int cc   = c & 511;                                                     \
            int row  = cc >> 2, g = cc & 3;                                         \
            uint32_t d = sb + (bufsel) * GSTG + tile * GTILE + row * 80 + g * 16;   \
            const char* s = srcs[tile] + ((size_t)row * K + (kc) * GBK) * 2 + g * 16; \
            asm volatile("cp.async.ca.shared.global [%0], [%1], 16;" :: "r"(d), "l"(s)); \
        }                                                                           \
        asm volatile("cp.async.commit_group;" ::: "memory");                        \
    }

    float acc[4][4][4];
#pragma unroll
    for (int i = 0; i < 4; i++)
#pragma unroll
        for (int j = 0; j < 4; j++)
#pragma unroll
            for (int r = 0; r < 4; r++) acc[i][j][r] = 0.0f;

    int nk = K / GBK;
    LOAD_STAGE(0, 0);
    LOAD_STAGE(1, 1);

    for (int kc = 0; kc < nk; kc++) {
        if (kc + 1 < nk)
            asm volatile("cp.async.wait_group 1;" ::: "memory");
        else
            asm volatile("cp.async.wait_group 0;" ::: "memory");
        __syncthreads();

        int buf = kc & 1;
        uint32_t bA = sb + buf * GSTG;
        uint32_t bB = bA + GTILE;

        uint32_t aoff = (uint32_t)(wm * 64 + (lane & 15)) * 80 + (lane >> 4) * 16;
        uint32_t boff = (uint32_t)(wn * 32 + (lane & 7)) * 80 + ((lane >> 3) & 1) * 16;

#pragma unroll
        for (int ks = 0; ks < 2; ks++) {
            uint32_t ko = ks * 32;
            uint32_t af[4][4];
#pragma unroll
            for (int mt = 0; mt < 4; mt++) {
                asm volatile("ldmatrix.sync.aligned.m8n8.x4.shared.b16 {%0,%1,%2,%3}, [%4];"
                    : "=r"(af[mt][0]), "=r"(af[mt][1]), "=r"(af[mt][2]), "=r"(af[mt][3])
                    : "r"(bA + aoff + ko + mt * (16 * 80)));
            }
            uint32_t bfr[4][2];
#pragma unroll
            for (int nt = 0; nt < 4; nt++) {
                asm volatile("ldmatrix.sync.aligned.m8n8.x2.shared.b16 {%0,%1}, [%2];"
                    : "=r"(bfr[nt][0]), "=r"(bfr[nt][1]) : "r"(bB + boff + ko + nt * (8 * 80)));
            }
#pragma unroll
            for (int mt = 0; mt < 4; mt++)
#pragma unroll
                for (int nt = 0; nt < 4; nt++) {
                    asm volatile(
                        "mma.sync.aligned.m16n8k16.row.col.f32.f16.f16.f32 "
                        "{%0,%1,%2,%3}, {%4,%5,%6,%7}, {%8,%9}, {%0,%1,%2,%3};"
                        : "+f"(acc[mt][nt][0]), "+f"(acc[mt][nt][1]),
                          "+f"(acc[mt][nt][2]), "+f"(acc[mt][nt][3])
                        : "r"(af[mt][0]), "r"(af[mt][1]), "r"(af[mt][2]), "r"(af[mt][3]),
                          "r"(bfr[nt][0]), "r"(bfr[nt][1]));
                }
        }
        __syncthreads();
        if (kc + 2 < nk) LOAD_STAGE(kc + 2, buf);
    }

#pragma unroll
    for (int mt = 0; mt < 4; mt++) {
        int r0 = m0 + wm * 64 + mt * 16 + gid;
#pragma unroll
        for (int nt = 0; nt < 4; nt++) {
            int cl = wn * 32 + nt * 8 + 2 * tg;
            float b0 = shb[cl], b1 = shb[cl + 1];
            *(float2*)(C + (size_t)r0 * N + n0 + cl) =
                make_float2(acc[mt][nt][0] + b0, acc[mt][nt][1] + b1);
            *(float2*)(C + (size_t)(r0 + 8) * N + n0 + cl) =
                make_float2(acc[mt][nt][2] + b0, acc[mt][nt][3] + b1);
        }
    }
}

// ---------------- persistent LSTM layer: two-phase batch pipeline ----------------
// Grid 128 = dir(2) x us(32: 16 units) x bs(2: 32 batches). Each step runs two
// 16-batch phases with separate barriers; the wait for phase X's barrier is
// issued one full phase after its arrivals -> barrier latency hidden.
// Mainloop per phase: 8 warps = 2(m: 32 gate-rows) x 4(k-split of 128), N=16.
#define RP     1040
#define OFF_A  0
#define OFF_B  (64 * RP)                      // h tile: 16 rows
#define OFF_G  (64 * RP + 16 * RP)            // 4 k-partial buffers
#define GPR    (64 * 17)                      // floats per partial buffer
#define RK_SMEM (OFF_G + 4 * GPR * 4)         // 100608

__global__ __launch_bounds__(256, 1) void lstm_layer_tc(
    const float* __restrict__ gates_f,
    const float* __restrict__ gates_r,
    const __half* __restrict__ Whf16f, const __half* __restrict__ Whf16r,
    __half* __restrict__ sh16,
    void* __restrict__ outbuf,
    int out_mode)
{
    extern __shared__ char sm[];
    uint32_t sb = smem_u32(sm);
    int tid  = threadIdx.x;
    int lane = tid & 31;
    int warp = tid >> 5;
    int gid  = lane >> 2;
    int tg   = lane & 3;

    int bx  = blockIdx.x;
    int dir = bx >> 6;
    int us  = (bx >> 1) & 31;
    int bs  = bx & 1;
    int u0  = us * 16;
    int b0  = bs * 32;

    unsigned* barP[2];
    barP[0] = &g_bar8[((dir * 2 + bs) * 2 + 0) * 32];
    barP[1] = &g_bar8[((dir * 2 + bs) * 2 + 1) * 32];

    const float* gates = dir ? gates_r : gates_f;
    const __half* wh = dir ? Whf16r : Whf16f;

    // ---- stage Whh slice once ----
#pragma unroll
    for (int j = 0; j < 16; j++) {
        int idx = tid + j * 256;
        int row = idx >> 6;
        int ch  = idx & 63;
        int g   = row >> 4;
        int ul  = row & 15;
        size_t soff = (size_t)(g * HH + u0 + ul) * HH + ch * 8;
        *(uint4*)(sm + OFF_A + row * RP + ch * 16) = *(const uint4*)(wh + soff);
    }

    int wk = warp >> 1;    // 0..3 k-split
    int wm = warp & 1;     // 0..1 m-half
    uint32_t apat = (uint32_t)(lane & 15) * RP + (lane >> 4) * 16;
    uint32_t bpat = (uint32_t)((lane & 7) + ((lane >> 4) << 3)) * RP + ((lane >> 3) & 1) * 16;
    uint32_t aBase = sb + OFF_A + wm * 32 * RP + apat;
    uint32_t bBase = sb + OFF_B + bpat;
    float* gk   = (float*)(sm + OFF_G) + wk * GPR;
    float* gAll = (float*)(sm + OFF_G);

    int bown = tid >> 4;   // 0..15 (batch within phase)
    int uown = tid & 15;   // 0..15 (unit)
    float cst[2] = {0.0f, 0.0f};

    for (int s = 0; s < LL; s++) {
        int t   = dir ? (LL - 1 - s) : s;
        int par = s & 1;
        const __half* hin  = sh16 + ((dir * 2 + par) * BB) * HH;
        __half*       hout = sh16 + ((dir * 2 + (par ^ 1)) * BB) * HH;

#pragma unroll
        for (int ph = 0; ph < 2; ph++) {
            int pb0 = b0 + ph * 16;
            unsigned* bar = barP[ph];

            // ---- wait for this phase's h(s) (arrivals of step s-1) ----
            if (tid == 0 && s > 0) {
                unsigned target = (unsigned)s * 32u;
                unsigned v;
                do {
                    asm volatile("ld.acquire.gpu.global.u32 %0, [%1];"
                                 : "=r"(v) : "l"(bar) : "memory");
                } while (v < target);
            }
            __syncthreads();

            // ---- prefetch this thread's 4 gate inputs ----
            float pg[4];
            {
                size_t gbase = ((size_t)t * BB + (pb0 + bown)) * G4 + (u0 + uown);
#pragma unroll
                for (int g = 0; g < 4; g++)
                    pg[g] = __ldcg(&gates[gbase + g * HH]);
            }

            // ---- stage h tile (16 b x 512 fp16) ----
#pragma unroll
            for (int j = 0; j < 4; j++) {
                int idx = tid + j * 256;       // 0..1023
                int row = idx >> 6;            // 0..15
                int ch  = idx & 63;
                uint4 v = __ldcg((const uint4*)(hin + (size_t)(pb0 + row) * HH + ch * 8));
                *(uint4*)(sm + OFF_B + row * RP + ch * 16) = v;
            }
            __syncthreads();

            // ---- mainloop: this warp's 8 k-chunks ----
            float t0[2][2][4];
#pragma unroll
            for (int i = 0; i < 2; i++)
#pragma unroll
                for (int j = 0; j < 2; j++)
#pragma unroll
                    for (int r = 0; r < 4; r++) t0[i][j][r] = 0.f;

#pragma unroll
            for (int kc = 0; kc < 8; kc++) {
                uint32_t kb = (uint32_t)(wk * 8 + kc) * 32;
                uint32_t af[2][4];
#pragma unroll
                for (int mt = 0; mt < 2; mt++) {
                    asm volatile("ldmatrix.sync.aligned.m8n8.x4.shared.b16 {%0,%1,%2,%3}, [%4];"
                        : "=r"(af[mt][0]), "=r"(af[mt][1]), "=r"(af[mt][2]), "=r"(af[mt][3])
                        : "r"(aBase + kb + mt * (16 * RP)));
                }
                uint32_t bf[4];
                asm volatile("ldmatrix.sync.aligned.m8n8.x4.shared.b16 {%0,%1,%2,%3}, [%4];"
                    : "=r"(bf[0]), "=r"(bf[1]), "=r"(bf[2]), "=r"(bf[3]) : "r"(bBase + kb));
#pragma unroll
                for (int mt = 0; mt < 2; mt++)
#pragma unroll
                    for (int nf = 0; nf < 2; nf++) {
                        asm volatile(
                            "mma.sync.aligned.m16n8k16.row.col.f32.f16.f16.f32 "
                            "{%0,%1,%2,%3}, {%4,%5,%6,%7}, {%8,%9}, {%0,%1,%2,%3};"
                            : "+f"(t0[mt][nf][0]), "+f"(t0[mt][nf][1]),
                              "+f"(t0[mt][nf][2]), "+f"(t0[mt][nf][3])
                            : "r"(af[mt][0]), "r"(af[mt][1]), "r"(af[mt][2]), "r"(af[mt][3]),
                              "r"(bf[nf * 2]), "r"(bf[nf * 2 + 1]));
                    }
            }

            // ---- write k-partials (scalar; pitch 17 odd) ----
#pragma unroll
            for (int mt = 0; mt < 2; mt++) {
                int r0 = wm * 32 + mt * 16 + gid;
#pragma unroll
                for (int nf = 0; nf < 2; nf++) {
                    int cl = nf * 8 + 2 * tg;
                    gk[r0 * 17 + cl]           = t0[mt][nf][0];
                    gk[r0 * 17 + cl + 1]       = t0[mt][nf][1];
                    gk[(r0 + 8) * 17 + cl]     = t0[mt][nf][2];
                    gk[(r0 + 8) * 17 + cl + 1] = t0[mt][nf][3];
                }
            }
            __syncthreads();

            // ---- epilogue: one (b,u) per thread ----
            {
                float gv[4];
#pragma unroll
                for (int g = 0; g < 4; g++) {
                    int row = g * 16 + uown;
                    float a = gAll[0 * GPR + row * 17 + bown]
                            + gAll[1 * GPR + row * 17 + bown]
                            + gAll[2 * GPR + row * 17 + bown]
                            + gAll[3 * GPR + row * 17 + bown];
                    gv[g] = pg[g] + a;
                }
                float si = fsig(gv[0]);
                float sf = fsig(gv[1]);
                float so = fsig(gv[3]);
                cst[ph] = sf * cst[ph] + si * ftanh(gv[2]);
                float h2 = so * ftanh(cst[ph]);
                int bg = pb0 + bown;
                __half hv = __float2half_rn(h2);
                hout[(size_t)bg * HH + u0 + uown] = hv;
                if (out_mode) {
                    size_t orow = (size_t)bg * LL + t;
                    ((float*)outbuf)[orow * (2 * HH) + dir * HH + u0 + uown] = h2;
                } else {
                    size_t orow = (size_t)t * BB + bg;
                    ((__half*)outbuf)[orow * (2 * HH) + dir * HH + u0 + uown] = hv;
                }
            }
            __syncthreads();

            // ---- arrive this phase's barrier ----
            if (tid == 0)
                asm volatile("red.release.gpu.global.add.u32 [%0], %1;"
                             :: "l"(bar), "r"(1u) : "memory");
        }
    }
}

// ---------------- host launcher ----------------
extern "C" void kernel_launch(void* const* d_in, const int* in_sizes, int n_in,
                              void* d_out, int out_size)
{
    const float* x       = (const float*)d_in[0];
    const float* Wih_f0  = (const float*)d_in[1];
    const float* Whh_f0  = (const float*)d_in[2];
    const float* bih_f0  = (const float*)d_in[3];
    const float* bhh_f0  = (const float*)d_in[4];
    const float* Wih_r0  = (const float*)d_in[5];
    const float* Whh_r0  = (const float*)d_in[6];
    const float* bih_r0  = (const float*)d_in[7];
    const float* bhh_r0  = (const float*)d_in[8];
    const float* Wih_f1  = (const float*)d_in[9];
    const float* Whh_f1  = (const float*)d_in[10];
    const float* bih_f1  = (const float*)d_in[11];
    const float* bhh_f1  = (const float*)d_in[12];
    const float* Wih_r1  = (const float*)d_in[13];
    const float* Whh_r1  = (const float*)d_in[14];
    const float* bih_r1  = (const float*)d_in[15];
    const float* bhh_r1  = (const float*)d_in[16];

    float *gf, *gr;
    unsigned* bar8;
    __half *Af16, *Wf16f, *Wf16r, *Whf16f, *Whf16r, *sh16;
    cudaGetSymbolAddress((void**)&gf,     g_gates_f);
    cudaGetSymbolAddress((void**)&gr,     g_gates_r);
    cudaGetSymbolAddress((void**)&bar8,   g_bar8);
    cudaGetSymbolAddress((void**)&Af16,   g_Af16);
    cudaGetSymbolAddress((void**)&Wf16f,  g_Wf16f);
    cudaGetSymbolAddress((void**)&Wf16r,  g_Wf16r);
    cudaGetSymbolAddress((void**)&Whf16f, g_Whf16f);
    cudaGetSymbolAddress((void**)&Whf16r, g_Whf16r);
    cudaGetSymbolAddress((void**)&sh16,   g_sh16);

    cudaFuncSetAttribute(gemm_f16,      cudaFuncAttributeMaxDynamicSharedMemorySize, GB_SMEM);
    cudaFuncSetAttribute(lstm_layer_tc, cudaFuncAttributeMaxDynamicSharedMemorySize, RK_SMEM);

    const int M = LL * BB;   // 32768
    const int whn4 = (G4 * HH) / 4;

    transpose_cvt_x<<<8192, 256>>>((const float4*)x, (__half2*)Af16);

    dim3 ggrid(G4 / 128, M / 128);   // (16, 256)

    // ---- layer 0 (K = 256) ----
    {
        int w4 = (G4 * II) / 4;
        cvt_f16<<<(w4 + 255) / 256, 256>>>((const float4*)Wih_f0, (__half2*)Wf16f, w4);
        cvt_f16<<<(w4 + 255) / 256, 256>>>((const float4*)Wih_r0, (__half2*)Wf16r, w4);
        gemm_f16<<<ggrid, 256, GB_SMEM>>>(M, G4, II, Af16, Wf16f, bih_f0, bhh_f0, gf);
        gemm_f16<<<ggrid, 256, GB_SMEM>>>(M, G4, II, Af16, Wf16r, bih_r0, bhh_r0, gr);
        cvt_f16<<<(whn4 + 255) / 256, 256>>>((const float4*)Whh_f0, (__half2*)Whf16f, whn4);
        cvt_f16<<<(whn4 + 255) / 256, 256>>>((const float4*)Whh_r0, (__half2*)Whf16r, whn4);
    }
    cudaMemsetAsync(sh16, 0, sizeof(__half) * 2 * 2 * BB * HH, 0);
    cudaMemsetAsync(bar8, 0, sizeof(unsigned) * 8 * 32, 0);
    lstm_layer_tc<<<128, 256, RK_SMEM>>>(gf, gr, Whf16f, Whf16r, sh16, Af16, 0);

    // ---- layer 1 (K = 1024) ----
    {
        int w4 = (G4 * 2 * HH) / 4;
        cvt_f16<<<(w4 + 255) / 256, 256>>>((const float4*)Wih_f1, (__half2*)Wf16f, w4);
        cvt_f16<<<(w4 + 255) / 256, 256>>>((const float4*)Wih_r1, (__half2*)Wf16r, w4);
        gemm_f16<<<ggrid, 256, GB_SMEM>>>(M, G4, 2 * HH, Af16, Wf16f, bih_f1, bhh_f1, gf);
        gemm_f16<<<ggrid, 256, GB_SMEM>>>(M, G4, 2 * HH, Af16, Wf16r, bih_r1, bhh_r1, gr);
        cvt_f16<<<(whn4 + 255) / 256, 256>>>((const float4*)Whh_f1, (__half2*)Whf16f, whn4);
        cvt_f16<<<(whn4 + 255) / 256, 256>>>((const float4*)Whh_r1, (__half2*)Whf16r, whn4);
    }
    cudaMemsetAsync(sh16, 0, sizeof(__half) * 2 * 2 * BB * HH, 0);
    cudaMemsetAsync(bar8, 0, sizeof(unsigned) * 8 * 32, 0);
    lstm_layer_tc<<<128, 256, RK_SMEM>>>(gf, gr, Whf16f, Whf16r, sh16, d_out, 1);
}

// round 16
// speedup vs baseline: 1.9002x; 1.9002x over previous
#include <cuda_runtime.h>
#include <cuda_bf16.h>
#include <cuda_fp16.h>
#include <math.h>
#include <cstdint>

// Problem dims
#define LL 512
#define BB 64
#define II 256
#define HH 512
#define G4 2048   // 4*H

// ---------------- scratch (static device globals; no allocation) ----------------
__device__ float g_gates_f[(size_t)LL * BB * G4];     // [t][b][4H]
__device__ float g_gates_r[(size_t)LL * BB * G4];     // [t][b][4H]
__device__ unsigned g_bar4[4 * 32];                   // 4 group barriers, 128B apart

// h state as SINGLE fp16: [dir][parity][b][u]
__device__ __align__(16) __half g_sh16[2 * 2 * BB * HH];

// fp16 GEMM operands: A single (layer0: xT fp16; layer1: hcat fp16), W single per dir
__device__ __align__(16) __half g_Af16[(size_t)LL * BB * 2 * HH];
__device__ __align__(16) __half g_Wf16f[(size_t)G4 * 2 * HH];
__device__ __align__(16) __half g_Wf16r[(size_t)G4 * 2 * HH];
// Whh fp16 (single) for the recurrence ([2048][512] each)
__device__ __align__(16) __half g_Whf16f[(size_t)G4 * HH];
__device__ __align__(16) __half g_Whf16r[(size_t)G4 * HH];

__device__ __forceinline__ uint32_t smem_u32(const void* p) {
    uint32_t a;
    asm("{ .reg .u64 t; cvta.to.shared.u64 t, %1; cvt.u32.u64 %0, t; }" : "=r"(a) : "l"(p));
    return a;
}

__device__ __forceinline__ float fsig(float x) {
    return 1.0f / (1.0f + __expf(-x));
}
__device__ __forceinline__ float ftanh(float x) {
    return fmaf(2.0f, fsig(2.0f * x), -1.0f);
}

// ---------------- transpose + convert: x[b][l][i] fp32 -> Af16[l*BB+b][i] fp16 ----------------
__global__ void transpose_cvt_x(const float4* __restrict__ x, __half2* __restrict__ xT) {
    int idx = blockIdx.x * blockDim.x + threadIdx.x;
    int i4 = idx & 63;
    int m  = idx >> 6;
    int t  = m >> 6;
    int b  = m & 63;
    float4 v = x[((size_t)(b * LL + t)) * 64 + i4];
    xT[idx * 2 + 0] = __floats2half2_rn(v.x, v.y);
    xT[idx * 2 + 1] = __floats2half2_rn(v.z, v.w);
}

// ---------------- fp32 -> fp16 convert ----------------
__global__ void cvt_f16(const float4* __restrict__ src, __half2* __restrict__ dst, int n4) {
    int i = blockIdx.x * blockDim.x + threadIdx.x;
    if (i >= n4) return;
    float4 v = src[i];
    dst[i * 2 + 0] = __floats2half2_rn(v.x, v.y);
    dst[i * 2 + 1] = __floats2half2_rn(v.z, v.w);
}

// ---------------- plain fp16 GEMM (unchanged, known-good) ----------------
#define GBK   32
#define GTILE 10240
#define GSTG  (2 * GTILE)
#define GB_SMEM (2 * GSTG + 512)

__global__ __launch_bounds__(256, 2) void gemm_f16(
    int M, int N, int K,
    const __half* __restrict__ A,
    const __half* __restrict__ B,
    const float* __restrict__ bias1, const float* __restrict__ bias2,
    float* __restrict__ C)
{
    extern __shared__ char sm[];
    uint32_t sb = smem_u32(sm);
    int tid  = threadIdx.x;
    int lane = tid & 31;
    int warp = tid >> 5;
    int gid  = lane >> 2;
    int tg   = lane & 3;
    int wm   = warp >> 2;
    int wn   = warp & 3;
    int n0   = blockIdx.x * 128;
    int m0   = blockIdx.y * 128;

    float* shb = (float*)(sm + 2 * GSTG);
    if (tid < 128) shb[tid] = bias1[n0 + tid] + bias2[n0 + tid];

    const char* srcs[2];
    srcs[0] = (const char*)(A + (size_t)m0 * K);
    srcs[1] = (const char*)(B + (size_t)n0 * K);

#define LOAD_STAGE(kc, bufsel)                                                      \
    {                                                                               \
        _Pragma("unroll")                                                           \
        for (int j = 0; j < 4; j++) {                                               \
            int c    = tid + j * 256;                                               \
            int tile = c >> 9;                                                      \
            int cc   = c & 511;                                                     \
            int row  = cc >> 2, g = cc & 3;                                         \
            uint32_t d = sb + (bufsel) * GSTG + tile * GTILE + row * 80 + g * 16;   \
            const char* s = srcs[tile] + ((size_t)row * K + (kc) * GBK) * 2 + g * 16; \
            asm volatile("cp.async.ca.shared.global [%0], [%1], 16;" :: "r"(d), "l"(s)); \
        }                                                                           \
        asm volatile("cp.async.commit_group;" ::: "memory");                        \
    }

    float acc[4][4][4];
#pragma unroll
    for (int i = 0; i < 4; i++)
#pragma unroll
        for (int j = 0; j < 4; j++)
#pragma unroll
            for (int r = 0; r < 4; r++) acc[i][j][r] = 0.0f;

    int nk = K / GBK;
    LOAD_STAGE(0, 0);
    LOAD_STAGE(1, 1);

    for (int kc = 0; kc < nk; kc++) {
        if (kc + 1 < nk)
            asm volatile("cp.async.wait_group 1;" ::: "memory");
        else
            asm volatile("cp.async.wait_group 0;" ::: "memory");
        __syncthreads();

        int buf = kc & 1;
        uint32_t bA = sb + buf * GSTG;
        uint32_t bB = bA + GTILE;

        uint32_t aoff = (uint32_t)(wm * 64 + (lane & 15)) * 80 + (lane >> 4) * 16;
        uint32_t boff = (uint32_t)(wn * 32 + (lane & 7)) * 80 + ((lane >> 3) & 1) * 16;

#pragma unroll
        for (int ks = 0; ks < 2; ks++) {
            uint32_t ko = ks * 32;
            uint32_t af[4][4];
#pragma unroll
            for (int mt = 0; mt < 4; mt++) {
                asm volatile("ldmatrix.sync.aligned.m8n8.x4.shared.b16 {%0,%1,%2,%3}, [%4];"
                    : "=r"(af[mt][0]), "=r"(af[mt][1]), "=r"(af[mt][2]), "=r"(af[mt][3])
                    : "r"(bA + aoff + ko + mt * (16 * 80)));
            }
            uint32_t bfr[4][2];
#pragma unroll
            for (int nt = 0; nt < 4; nt++) {
                asm volatile("ldmatrix.sync.aligned.m8n8.x2.shared.b16 {%0,%1}, [%2];"
                    : "=r"(bfr[nt][0]), "=r"(bfr[nt][1]) : "r"(bB + boff + ko + nt * (8 * 80)));
            }
#pragma unroll
            for (int mt = 0; mt < 4; mt++)
#pragma unroll
                for (int nt = 0; nt < 4; nt++) {
                    asm volatile(
                        "mma.sync.aligned.m16n8k16.row.col.f32.f16.f16.f32 "
                        "{%0,%1,%2,%3}, {%4,%5,%6,%7}, {%8,%9}, {%0,%1,%2,%3};"
                        : "+f"(acc[mt][nt][0]), "+f"(acc[mt][nt][1]),
                          "+f"(acc[mt][nt][2]), "+f"(acc[mt][nt][3])
                        : "r"(af[mt][0]), "r"(af[mt][1]), "r"(af[mt][2]), "r"(af[mt][3]),
                          "r"(bfr[nt][0]), "r"(bfr[nt][1]));
                }
        }
        __syncthreads();
        if (kc + 2 < nk) LOAD_STAGE(kc + 2, buf);
    }

#pragma unroll
    for (int mt = 0; mt < 4; mt++) {
        int r0 = m0 + wm * 64 + mt * 16 + gid;
#pragma unroll
        for (int nt = 0; nt < 4; nt++) {
            int cl = wn * 32 + nt * 8 + 2 * tg;
            float b0 = shb[cl], b1 = shb[cl + 1];
            *(float2*)(C + (size_t)r0 * N + n0 + cl) =
                make_float2(acc[mt][nt][0] + b0, acc[mt][nt][1] + b1);
            *(float2*)(C + (size_t)(r0 + 8) * N + n0 + cl) =
                make_float2(acc[mt][nt][2] + b0, acc[mt][nt][3] + b1);
        }
    }
}

// ---------------- persistent LSTM layer: R14 structure, 2 CTAs/SM ----------------
// Grid 128 = dir(2) x us(32: 16 units) x bs(2: 32 batches). 2 CTAs co-resident
// per SM: one CTA's barrier poll / h staging overlaps the partner's MMA.
// 8 warps = 4(m: 16 gate-rows) x 2(n: 16 batches), full K per warp -> single
// gate-partial buffer; smem 108,288 B (x2 = 216.6KB <= 227KB).
#define RP     1040
#define OFF_A  0
#define OFF_B  (64 * RP)
#define OFF_G  (64 * RP + 32 * RP)
#define RK_SMEM (OFF_G + 64 * 33 * 4)        // 108288

__global__ __launch_bounds__(256, 2) void lstm_layer_tc(
    const float* __restrict__ gates_f,
    const float* __restrict__ gates_r,
    const __half* __restrict__ Whf16f, const __half* __restrict__ Whf16r,
    __half* __restrict__ sh16,
    void* __restrict__ outbuf,
    int out_mode)
{
    extern __shared__ char sm[];
    uint32_t sb = smem_u32(sm);
    int tid  = threadIdx.x;
    int lane = tid & 31;
    int warp = tid >> 5;
    int gid  = lane >> 2;
    int tg   = lane & 3;

    int bx  = blockIdx.x;
    int dir = bx >> 6;
    int us  = (bx >> 1) & 31;
    int bs  = bx & 1;
    int u0  = us * 16;
    int b0  = bs * 32;
    int grp = dir * 2 + bs;
    unsigned* gbar = (unsigned*)&g_bar4[grp * 32];

    const float* gates = dir ? gates_r : gates_f;
    const __half* wh = dir ? Whf16r : Whf16f;

    // ---- stage Whh slice once (single fp16) ----
#pragma unroll
    for (int j = 0; j < 16; j++) {
        int idx = tid + j * 256;
        int row = idx >> 6;
        int ch  = idx & 63;
        int g   = row >> 4;
        int ul  = row & 15;
        size_t soff = (size_t)(g * HH + u0 + ul) * HH + ch * 8;
        *(uint4*)(sm + OFF_A + row * RP + ch * 16) = *(const uint4*)(wh + soff);
    }

    // 8 warps = 4m x 2n
    int wm = warp >> 1;    // 0..3: 16 gate-rows each
    int wn = warp & 1;     // 0..1: 16 batches each
    uint32_t apat = (uint32_t)(lane & 15) * RP + (lane >> 4) * 16;
    uint32_t bpat = (uint32_t)((lane & 7) + ((lane >> 4) << 3)) * RP + ((lane >> 3) & 1) * 16;
    uint32_t aBase = sb + OFF_A + wm * 16 * RP + apat;
    uint32_t bBase = sb + OFF_B + wn * 16 * RP + bpat;
    float* gbuf = (float*)(sm + OFF_G);

    int bown = tid >> 3;
    int u2   = (tid & 7) * 2;
    float cst0 = 0.0f, cst1 = 0.0f;

    for (int s = 0; s < LL; s++) {
        int t   = dir ? (LL - 1 - s) : s;
        int par = s & 1;
        const __half* hin  = sh16 + ((dir * 2 + par) * BB) * HH;
        __half*       hout = sh16 + ((dir * 2 + (par ^ 1)) * BB) * HH;

        // ---- prefetch this thread's gate inputs (float2 per gate) ----
        float2 pg[4];
        {
            size_t gbase = ((size_t)t * BB + (b0 + bown)) * G4 + (u0 + u2);
#pragma unroll
            for (int g = 0; g < 4; g++)
                pg[g] = __ldcg((const float2*)&gates[gbase + g * HH]);
        }

        // ---- stage h tile (32 b x 512 fp16) ----
#pragma unroll
        for (int j = 0; j < 8; j++) {
            int idx = tid + j * 256;
            int row = idx >> 6;
            int ch  = idx & 63;
            uint4 v = __ldcg((const uint4*)(hin + (size_t)(b0 + row) * HH + ch * 8));
            *(uint4*)(sm + OFF_B + row * RP + ch * 16) = v;
        }
        __syncthreads();

        // ---- single-term HMMA: this warp runs all 32 k-chunks ----
        float t0[2][4];
#pragma unroll
        for (int j = 0; j < 2; j++)
#pragma unroll
            for (int r = 0; r < 4; r++) t0[j][r] = 0.f;

#pragma unroll 8
        for (int kc = 0; kc < 32; kc++) {
            uint32_t kb = (uint32_t)kc * 32;
            uint32_t af[4];
            asm volatile("ldmatrix.sync.aligned.m8n8.x4.shared.b16 {%0,%1,%2,%3}, [%4];"
                : "=r"(af[0]), "=r"(af[1]), "=r"(af[2]), "=r"(af[3])
                : "r"(aBase + kb));
            uint32_t bf[4];
            asm volatile("ldmatrix.sync.aligned.m8n8.x4.shared.b16 {%0,%1,%2,%3}, [%4];"
                : "=r"(bf[0]), "=r"(bf[1]), "=r"(bf[2]), "=r"(bf[3]) : "r"(bBase + kb));
#pragma unroll
            for (int nf = 0; nf < 2; nf++) {
                asm volatile(
                    "mma.sync.aligned.m16n8k16.row.col.f32.f16.f16.f32 "
                    "{%0,%1,%2,%3}, {%4,%5,%6,%7}, {%8,%9}, {%0,%1,%2,%3};"
                    : "+f"(t0[nf][0]), "+f"(t0[nf][1]),
                      "+f"(t0[nf][2]), "+f"(t0[nf][3])
                    : "r"(af[0]), "r"(af[1]), "r"(af[2]), "r"(af[3]),
                      "r"(bf[nf * 2]), "r"(bf[nf * 2 + 1]));
            }
        }

        // ---- write partials to gate buffer (scalar: pitch 33 odd) ----
        {
            int r0 = wm * 16 + gid;
#pragma unroll
            for (int nf = 0; nf < 2; nf++) {
                int cl = wn * 16 + nf * 8 + 2 * tg;
                gbuf[r0 * 33 + cl]           = t0[nf][0];
                gbuf[r0 * 33 + cl + 1]       = t0[nf][1];
                gbuf[(r0 + 8) * 33 + cl]     = t0[nf][2];
                gbuf[(r0 + 8) * 33 + cl + 1] = t0[nf][3];
            }
        }
        __syncthreads();

        // ---- epilogue: two units (u2, u2+1) of batch bown; direct writeback ----
        {
            float a0[4], a1[4];
#pragma unroll
            for (int g = 0; g < 4; g++) {
                int r0 = g * 16 + u2;
                a0[g] = gbuf[r0 * 33 + bown];
                a1[g] = gbuf[(r0 + 1) * 33 + bown];
            }
            float gi0 = pg[0].x + a0[0], gi1 = pg[0].y + a1[0];
            float gf0 = pg[1].x + a0[1], gf1 = pg[1].y + a1[1];
            float gg0 = pg[2].x + a0[2], gg1 = pg[2].y + a1[2];
            float go0 = pg[3].x + a0[3], go1 = pg[3].y + a1[3];
            float si0 = fsig(gi0), si1 = fsig(gi1);
            float sf0 = fsig(gf0), sf1 = fsig(gf1);
            float so0 = fsig(go0), so1 = fsig(go1);
            cst0 = sf0 * cst0 + si0 * ftanh(gg0);
            cst1 = sf1 * cst1 + si1 * ftanh(gg1);
            float h20 = so0 * ftanh(cst0);
            float h21 = so1 * ftanh(cst1);
            int bg = b0 + bown;
            size_t hoff = (size_t)bg * HH + u0 + u2;
            __half2 hp = __floats2half2_rn(h20, h21);
            __stcg((__half2*)&hout[hoff], hp);
            if (out_mode) {
                size_t orow = (size_t)bg * LL + t;
                *(float2*)((float*)outbuf + orow * (2 * HH) + dir * HH + u0 + u2) =
                    make_float2(h20, h21);
            } else {
                size_t orow = (size_t)t * BB + bg;
                *((__half2*)((__half*)outbuf + orow * (2 * HH) + dir * HH + u0 + u2)) = hp;
            }
        }

        // ---- group barrier across 32 CTAs ----
        __syncthreads();
        if (tid == 0) {
            unsigned target = (unsigned)(s + 1) * 32u;
            asm volatile("red.release.gpu.global.add.u32 [%0], %1;"
                         :: "l"(gbar), "r"(1u) : "memory");
            unsigned v;
            do {
                asm volatile("ld.acquire.gpu.global.u32 %0, [%1];"
                             : "=r"(v) : "l"(gbar) : "memory");
            } while (v < target);
        }
        __syncthreads();
    }
}

// ---------------- host launcher ----------------
extern "C" void kernel_launch(void* const* d_in, const int* in_sizes, int n_in,
                              void* d_out, int out_size)
{
    const float* x       = (const float*)d_in[0];
    const float* Wih_f0  = (const float*)d_in[1];
    const float* Whh_f0  = (const float*)d_in[2];
    const float* bih_f0  = (const float*)d_in[3];
    const float* bhh_f0  = (const float*)d_in[4];
    const float* Wih_r0  = (const float*)d_in[5];
    const float* Whh_r0  = (const float*)d_in[6];
    const float* bih_r0  = (const float*)d_in[7];
    const float* bhh_r0  = (const float*)d_in[8];
    const float* Wih_f1  = (const float*)d_in[9];
    const float* Whh_f1  = (const float*)d_in[10];
    const float* bih_f1  = (const float*)d_in[11];
    const float* bhh_f1  = (const float*)d_in[12];
    const float* Wih_r1  = (const float*)d_in[13];
    const float* Whh_r1  = (const float*)d_in[14];
    const float* bih_r1  = (const float*)d_in[15];
    const float* bhh_r1  = (const float*)d_in[16];

    float *gf, *gr;
    unsigned* bar4;
    __half *Af16, *Wf16f, *Wf16r, *Whf16f, *Whf16r, *sh16;
    cudaGetSymbolAddress((void**)&gf,     g_gates_f);
    cudaGetSymbolAddress((void**)&gr,     g_gates_r);
    cudaGetSymbolAddress((void**)&bar4,   g_bar4);
    cudaGetSymbolAddress((void**)&Af16,   g_Af16);
    cudaGetSymbolAddress((void**)&Wf16f,  g_Wf16f);
    cudaGetSymbolAddress((void**)&Wf16r,  g_Wf16r);
    cudaGetSymbolAddress((void**)&Whf16f, g_Whf16f);
    cudaGetSymbolAddress((void**)&Whf16r, g_Whf16r);
    cudaGetSymbolAddress((void**)&sh16,   g_sh16);

    cudaFuncSetAttribute(gemm_f16,      cudaFuncAttributeMaxDynamicSharedMemorySize, GB_SMEM);
    cudaFuncSetAttribute(lstm_layer_tc, cudaFuncAttributeMaxDynamicSharedMemorySize, RK_SMEM);

    const int M = LL * BB;   // 32768
    const int whn4 = (G4 * HH) / 4;

    transpose_cvt_x<<<8192, 256>>>((const float4*)x, (__half2*)Af16);

    dim3 ggrid(G4 / 128, M / 128);   // (16, 256)

    // ---- layer 0 (K = 256) ----
    {
        int w4 = (G4 * II) / 4;
        cvt_f16<<<(w4 + 255) / 256, 256>>>((const float4*)Wih_f0, (__half2*)Wf16f, w4);
        cvt_f16<<<(w4 + 255) / 256, 256>>>((const float4*)Wih_r0, (__half2*)Wf16r, w4);
        gemm_f16<<<ggrid, 256, GB_SMEM>>>(M, G4, II, Af16, Wf16f, bih_f0, bhh_f0, gf);
        gemm_f16<<<ggrid, 256, GB_SMEM>>>(M, G4, II, Af16, Wf16r, bih_r0, bhh_r0, gr);
        cvt_f16<<<(whn4 + 255) / 256, 256>>>((const float4*)Whh_f0, (__half2*)Whf16f, whn4);
        cvt_f16<<<(whn4 + 255) / 256, 256>>>((const float4*)Whh_r0, (__half2*)Whf16r, whn4);
    }
    cudaMemsetAsync(sh16, 0, sizeof(__half) * 2 * 2 * BB * HH, 0);
    cudaMemsetAsync(bar4, 0, sizeof(unsigned) * 4 * 32, 0);
    lstm_layer_tc<<<128, 256, RK_SMEM>>>(gf, gr, Whf16f, Whf16r, sh16, Af16, 0);

    // ---- layer 1 (K = 1024) ----
    {
        int w4 = (G4 * 2 * HH) / 4;
        cvt_f16<<<(w4 + 255) / 256, 256>>>((const float4*)Wih_f1, (__half2*)Wf16f, w4);
        cvt_f16<<<(w4 + 255) / 256, 256>>>((const float4*)Wih_r1, (__half2*)Wf16r, w4);
        gemm_f16<<<ggrid, 256, GB_SMEM>>>(M, G4, 2 * HH, Af16, Wf16f, bih_f1, bhh_f1, gf);
        gemm_f16<<<ggrid, 256, GB_SMEM>>>(M, G4, 2 * HH, Af16, Wf16r, bih_r1, bhh_r1, gr);
        cvt_f16<<<(whn4 + 255) / 256, 256>>>((const float4*)Whh_f1, (__half2*)Whf16f, whn4);
        cvt_f16<<<(whn4 + 255) / 256, 256>>>((const float4*)Whh_r1, (__half2*)Whf16r, whn4);
    }
    cudaMemsetAsync(sh16, 0, sizeof(__half) * 2 * 2 * BB * HH, 0);
    cudaMemsetAsync(bar4, 0, sizeof(unsigned) * 4 * 32, 0);
    lstm_layer_tc<<<128, 256, RK_SMEM>>>(gf, gr, Whf16f, Whf16r, sh16, d_out, 1);
}